// round 14
// baseline (speedup 1.0000x reference)
#include <cuda_runtime.h>
#include <cuda_fp16.h>
#include <cstdint>

// ============================================================================
// VectorQuantizer via mma.sync fp16 (f16 accum) screening GEMM + exact fp32
// rescore.
// R14: occupancy experiment — 1024-thread main CTA (32 warps = 8/SMSP, warp
//      tile 32x32, f16 accumulators per the R12-validated numerics, <=64 regs
//      via launch_bounds). Tests the per-warp-issue model (R4: 2 w/SMSP ->
//      28.5 cyc/HMMA; R5+: 4 w/SMSP -> 16) vs the hard-cap model.
//      Prep = R12 fp16 prep (zero_cnt fused); rescore = R13 batched verbatim.
// ============================================================================

#define N_ROWS   32768
#define CDIM     256
#define KCODES   8192
#define NSPLIT   8
#define KPER     (KCODES / NSPLIT)        // 1024
#define MT       256                      // rows per CTA
#define NT_TILE  128                      // codes per tile
#define NTILES   (KPER / NT_TILE)         // 8
#define NCHUNKS  (NTILES * 2)             // 16 (tile x k-half)
#define THREADS  1024
#define CAP      32
#define LCAP     24
#define SCAP     48
#define MARGIN   1.4e-4f
#define DEQ      (-2.44140625e-4f)        // -2 * 2^-13 (exact)

#define ASTRIDE  528                      // A smem row stride (bytes)
#define ABYTES   (MT * ASTRIDE)           // 135168
#define BSTRIDE  272                      // B chunk row stride (128 k = 256B)
#define BCHUNK   (NT_TILE * BSTRIDE)      // 34816
#define SMEM_BYTES (ABYTES + 2 * BCHUNK)  // 204800

typedef unsigned long long u64;

__device__ __half g_xh[(size_t)N_ROWS * CDIM];   // 16 MB
__device__ __half g_wh[(size_t)KCODES * CDIM];   //  4 MB (scaled by 2^13)
__device__ float g_xnorm[N_ROWS];
__device__ int   g_cnt[NSPLIT][N_ROWS];
__device__ float g_cs[NSPLIT][N_ROWS][CAP];
__device__ int   g_ci[NSPLIT][N_ROWS][CAP];

__device__ __forceinline__ uint32_t smem_u32(const void* p) {
    uint32_t a;
    asm("{ .reg .u64 t; cvta.to.shared.u64 t, %1; cvt.u32.u64 %0, t; }"
        : "=r"(a) : "l"(p));
    return a;
}
__device__ __forceinline__ void ldsm4(uint32_t* r, uint32_t addr) {
    asm volatile("ldmatrix.sync.aligned.m8n8.x4.shared.b16 {%0,%1,%2,%3}, [%4];"
                 : "=r"(r[0]), "=r"(r[1]), "=r"(r[2]), "=r"(r[3]) : "r"(addr));
}
// fp16 mma with fp16 accumulators (C/D = 2 regs).
__device__ __forceinline__ void mma_h(uint32_t* c, const uint32_t* a,
                                      uint32_t b0, uint32_t b1) {
    asm volatile(
        "mma.sync.aligned.m16n8k16.row.col.f16.f16.f16.f16 "
        "{%0,%1}, {%2,%3,%4,%5}, {%6,%7}, {%0,%1};"
        : "+r"(c[0]), "+r"(c[1])
        : "r"(a[0]), "r"(a[1]), "r"(a[2]), "r"(a[3]), "r"(b0), "r"(b1));
}
__device__ __forceinline__ void cp16(uint32_t saddr, const void* g) {
    asm volatile("cp.async.cg.shared.global [%0], [%1], 16;"
                 :: "r"(saddr), "l"(g) : "memory");
}
#define CP_COMMIT() asm volatile("cp.async.commit_group;" ::: "memory")
#define CP_WAIT0()  asm volatile("cp.async.wait_group 0;" ::: "memory")
#define CP_WAIT1()  asm volatile("cp.async.wait_group 1;" ::: "memory")

// ---------------------------------------------------------------------------
// Prep kernels (R12-validated fp16 screen inputs).
// ---------------------------------------------------------------------------
__global__ void vq_conv_w(const float* __restrict__ w) {
    int i = blockIdx.x * blockDim.x + threadIdx.x;
    const float4* wg = reinterpret_cast<const float4*>(w);
    float4 a = wg[2 * i], b = wg[2 * i + 1];
    const float S = 8192.0f;               // 2^13, exact
    __half2* o = reinterpret_cast<__half2*>(g_wh);
    o[4 * i + 0] = __floats2half2_rn(a.x * S, a.y * S);
    o[4 * i + 1] = __floats2half2_rn(a.z * S, a.w * S);
    o[4 * i + 2] = __floats2half2_rn(b.x * S, b.y * S);
    o[4 * i + 3] = __floats2half2_rn(b.z * S, b.w * S);
}
// xnorm reduction byte-identical to the passing version; fp16 conversion and
// g_cnt zeroing fused in.
__global__ void vq_prep_x(const float* __restrict__ x) {
    int row  = (blockIdx.x * blockDim.x + threadIdx.x) >> 5;
    int lane = threadIdx.x & 31;
    const float4* xr = reinterpret_cast<const float4*>(x + (size_t)row * CDIM);
    __half2* o = reinterpret_cast<__half2*>(g_xh + (size_t)row * CDIM);
    float s = 0.0f;
    #pragma unroll
    for (int i = 0; i < 2; ++i) {
        int j = lane + 32 * i;
        float4 v = xr[j];
        s = fmaf(v.x, v.x, s); s = fmaf(v.y, v.y, s);
        s = fmaf(v.z, v.z, s); s = fmaf(v.w, v.w, s);
        o[2 * j]     = __floats2half2_rn(v.x, v.y);
        o[2 * j + 1] = __floats2half2_rn(v.z, v.w);
    }
    #pragma unroll
    for (int of = 16; of > 0; of >>= 1) s += __shfl_xor_sync(0xffffffffu, s, of);
    if (lane == 0) g_xnorm[row] = s;
    if (lane < NSPLIT) g_cnt[lane][row] = 0;
}

// ---------------------------------------------------------------------------
// Screening GEMM. Grid (128 row-tiles, 8 splits), 1024 threads (32 warps,
// 8/SMSP). Warp grid 8(M) x 4(N); warp tile 32x32; f16 accumulators;
// A resident; B streamed as 16 chunks (128 codes x 128 k) cp.async ring.
// ---------------------------------------------------------------------------
__global__ void __launch_bounds__(THREADS, 1)
vq_main_kernel() {
    extern __shared__ char smem[];
    const uint32_t sA = smem_u32(smem);
    const uint32_t sB = sA + ABYTES;

    const int tid  = threadIdx.x;
    const int wid  = tid >> 5;
    const int lane = tid & 31;
    const int wm   = wid >> 2;            // 0..7  (32-row slabs)
    const int wn   = wid & 3;             // 0..3  (32-col slabs)
    const int m0   = blockIdx.x * MT;
    const int split = blockIdx.y;
    const char* whb = reinterpret_cast<const char*>(g_wh);

    // ---- A: 256 rows x 256 f16 into smem (stride 528B) ----
    const uint4* xh4 = reinterpret_cast<const uint4*>(g_xh);
    #pragma unroll
    for (int it = 0; it < 8; ++it) {
        int i = tid + it * THREADS;
        int r = i >> 5, c = i & 31;
        *reinterpret_cast<uint4*>(smem + r * ASTRIDE + c * 16) =
            xh4[(size_t)(m0 + r) * 32 + c];
    }

    // chunk loader: chunk c = (tile c>>1, k-half c&1), 2 cp16 per thread
    auto issue_chunk = [&](int c) {
        int g0 = split * KPER + (c >> 1) * NT_TILE;
        int h  = c & 1;
        uint32_t bs = sB + (uint32_t)((c & 1) * BCHUNK);
        #pragma unroll
        for (int it = 0; it < 2; ++it) {
            int i = tid + it * THREADS;
            int r = i >> 4, q = i & 15;
            cp16(bs + (uint32_t)(r * BSTRIDE + q * 16),
                 whb + (size_t)(g0 + r) * 512 + h * 256 + q * 16);
        }
        CP_COMMIT();
    };

    issue_chunk(0);
    issue_chunk(1);

    // per-lane ldmatrix base addresses
    const uint32_t aAddr = sA + (uint32_t)(wm * 32 + (lane & 15)) * ASTRIDE
                              + (uint32_t)((lane >> 4) << 4);
    const uint32_t bLane = (uint32_t)(wn * 32 + (lane & 7) + ((lane >> 4) << 3)) * BSTRIDE
                              + (uint32_t)(((lane >> 3) & 1) << 4);

    // xn for this lane's 4 rows (rsel = mf*2+h)
    float xnr[4];
    #pragma unroll
    for (int mf = 0; mf < 2; ++mf)
        #pragma unroll
        for (int h = 0; h < 2; ++h)
            xnr[mf * 2 + h] = g_xnorm[m0 + wm * 32 + mf * 16 + (lane >> 2) + h * 8];

    float run[4];
    #pragma unroll
    for (int i = 0; i < 4; ++i) run[i] = 3.4e38f;

    // thread-local candidate buffer (local memory; touched rarely)
    float lsc[LCAP];
    int   lci[LCAP];
    int   ltot = 0;

    // f16 accumulators: acc[mf][nf][h] = f16x2 (two adjacent cols, row-half h)
    uint32_t acc[2][4][2];
    #pragma unroll
    for (int mf = 0; mf < 2; ++mf)
        #pragma unroll
        for (int nf = 0; nf < 4; ++nf) {
            acc[mf][nf][0] = 0u;
            acc[mf][nf][1] = 0u;
        }

    for (int c = 0; c < NCHUNKS; ++c) {
        if (c < NCHUNKS - 1) CP_WAIT1(); else CP_WAIT0();
        __syncthreads();

        const uint32_t bBuf = sB + (uint32_t)((c & 1) * BCHUNK) + bLane;
        const uint32_t hOff = (uint32_t)((c & 1) * 256);   // A k-half byte off

        // ---- 8 k-steps over this chunk ----
        #pragma unroll
        for (int k = 0; k < 8; ++k) {
            const uint32_t ko = (uint32_t)(k * 32);
            uint32_t a[2][4], b[2][4];
            ldsm4(a[0], aAddr + hOff + ko);
            ldsm4(a[1], aAddr + (uint32_t)(16 * ASTRIDE) + hOff + ko);
            ldsm4(b[0], bBuf + ko);
            ldsm4(b[1], bBuf + (uint32_t)(16 * BSTRIDE) + ko);
            #pragma unroll
            for (int mf = 0; mf < 2; ++mf) {
                #pragma unroll
                for (int p = 0; p < 2; ++p) {
                    mma_h(acc[mf][p * 2 + 0], a[mf], b[p][0], b[p][1]);
                    mma_h(acc[mf][p * 2 + 1], a[mf], b[p][2], b[p][3]);
                }
            }
        }

        // ---- epilogue after the second k-half of each tile ----
        if (c & 1) {
            const int nt = c >> 1;
            const int nTileBase = split * KPER + nt * NT_TILE + wn * 32 + 2 * (lane & 3);
            #pragma unroll
            for (int mf = 0; mf < 2; ++mf) {
                #pragma unroll
                for (int h = 0; h < 2; ++h) {
                    const int rsel = mf * 2 + h;
                    float xnv = xnr[rsel];
                    float s[8];
                    float tmin = 3.4e38f;
                    #pragma unroll
                    for (int nf = 0; nf < 4; ++nf) {
                        __half2 hv = *reinterpret_cast<__half2*>(&acc[mf][nf][h]);
                        float2 fv = __half22float2(hv);
                        s[nf * 2]     = fmaf(DEQ, fv.x, xnv);
                        s[nf * 2 + 1] = fmaf(DEQ, fv.y, xnv);
                        tmin = fminf(tmin, fminf(s[nf * 2], s[nf * 2 + 1]));
                    }
                    float q = fminf(tmin, __shfl_xor_sync(0xffffffffu, tmin, 1));
                    q = fminf(q, __shfl_xor_sync(0xffffffffu, q, 2));
                    float thr = fminf(run[rsel], q) + MARGIN;
                    run[rsel] = fminf(run[rsel], q);
                    #pragma unroll
                    for (int nf = 0; nf < 4; ++nf) {
                        #pragma unroll
                        for (int j = 0; j < 2; ++j) {
                            if (s[nf * 2 + j] <= thr) {
                                if (ltot < LCAP) {
                                    lsc[ltot] = s[nf * 2 + j];
                                    lci[ltot] = (nTileBase + nf * 8 + j) | (rsel << 13);
                                }
                                ltot++;
                            }
                        }
                    }
                }
            }
            #pragma unroll
            for (int mf = 0; mf < 2; ++mf)
                #pragma unroll
                for (int nf = 0; nf < 4; ++nf) {
                    acc[mf][nf][0] = 0u;
                    acc[mf][nf][1] = 0u;
                }
        }

        __syncthreads();
        if (c + 2 < NCHUNKS) issue_chunk(c + 2);
    }

    // ---- flush thread-local candidates (re-filtered by final running min) ----
    {
        int rowbase[4];
        #pragma unroll
        for (int mf = 0; mf < 2; ++mf)
            #pragma unroll
            for (int h = 0; h < 2; ++h)
                rowbase[mf * 2 + h] = m0 + wm * 32 + mf * 16 + (lane >> 2) + h * 8;

        if (ltot > LCAP) {
            #pragma unroll
            for (int r = 0; r < 4; ++r)
                atomicAdd(&g_cnt[split][rowbase[r]], CAP + 1);
        } else {
            for (int j = 0; j < ltot; ++j) {
                float s  = lsc[j];
                int   e  = lci[j];
                int   rs = e >> 13;
                if (s <= run[rs] + MARGIN) {
                    int row = rowbase[rs];
                    int slot = atomicAdd(&g_cnt[split][row], 1);
                    if (slot < CAP) {
                        g_cs[split][row][slot] = s;
                        g_ci[split][row][slot] = e & 8191;
                    }
                }
            }
        }
    }
}

// ---------------------------------------------------------------------------
// Rescore + finalize (R13 batched version, verbatim). One warp per row.
// ---------------------------------------------------------------------------
__global__ void __launch_bounds__(256)
vq_rescore_kernel(const float* __restrict__ x, const float* __restrict__ w,
                  float* __restrict__ out) {
    __shared__ int slist_s[8][SCAP];
    int wid = threadIdx.x >> 5, lane = threadIdx.x & 31;
    int row = blockIdx.x * 8 + wid;
    int* slist = slist_s[wid];

    const float4* xr = reinterpret_cast<const float4*>(x + (size_t)row * CDIM);
    float4 xa = xr[lane * 2], xb = xr[lane * 2 + 1];
    float xn = g_xnorm[row];

    int   cnts[NSPLIT];
    float sl[NSPLIT];
    int   il[NSPLIT];
    float amin = 3.4e38f;
    #pragma unroll
    for (int sp = 0; sp < NSPLIT; ++sp) {
        int c = g_cnt[sp][row];
        cnts[sp] = c;
        sl[sp] = (c <= CAP && lane < c) ? g_cs[sp][row][lane] : 3.4e38f;
        il[sp] = (c <= CAP && lane < c) ? g_ci[sp][row][lane] : 0;
    }
    #pragma unroll
    for (int sp = 0; sp < NSPLIT; ++sp) {
        float s = sl[sp];
        #pragma unroll
        for (int o = 16; o > 0; o >>= 1)
            s = fminf(s, __shfl_xor_sync(0xffffffffu, s, o));
        amin = fminf(amin, s);
    }
    float thr = amin + MARGIN;

    int scnt = 0;
    bool scan_all = false;
    #pragma unroll
    for (int sp = 0; sp < NSPLIT; ++sp) {
        if (cnts[sp] > CAP) { scan_all = true; continue; }
        unsigned m = __ballot_sync(0xffffffffu, sl[sp] <= thr);
        while (m) {
            int b = __ffs(m) - 1;
            m &= m - 1;
            int k = __shfl_sync(0xffffffffu, il[sp], b);
            if (scnt < SCAP) slist[scnt] = k;
            scnt++;
        }
    }
    if (scnt > SCAP) scan_all = true;

    float bv = 3.4e38f;
    int   bi = 0x7fffffff;

    auto eval4 = [&](const int* kk, int nb) {
        float4 wa[4], wb[4];
        for (int t = 0; t < nb; ++t) {
            const float4* wr =
                reinterpret_cast<const float4*>(w + (size_t)kk[t] * CDIM);
            wa[t] = wr[lane * 2];
            wb[t] = wr[lane * 2 + 1];
        }
        float d[4];
        for (int t = 0; t < nb; ++t) {
            float dd = 0.0f;
            dd = fmaf(xa.x, wa[t].x, dd); dd = fmaf(xa.y, wa[t].y, dd);
            dd = fmaf(xa.z, wa[t].z, dd); dd = fmaf(xa.w, wa[t].w, dd);
            dd = fmaf(xb.x, wb[t].x, dd); dd = fmaf(xb.y, wb[t].y, dd);
            dd = fmaf(xb.z, wb[t].z, dd); dd = fmaf(xb.w, wb[t].w, dd);
            d[t] = dd;
        }
        #pragma unroll
        for (int o = 16; o > 0; o >>= 1)
            for (int t = 0; t < nb; ++t)
                d[t] += __shfl_xor_sync(0xffffffffu, d[t], o);
        for (int t = 0; t < nb; ++t) {
            float s = fmaf(-2.0f, d[t], xn);
            if (s < bv || (s == bv && kk[t] < bi)) { bv = s; bi = kk[t]; }
        }
    };

    if (scan_all) {
        int kk[4];
        for (int k = 0; k < KCODES; k += 4) {
            kk[0] = k; kk[1] = k + 1; kk[2] = k + 2; kk[3] = k + 3;
            eval4(kk, 4);
        }
    } else {
        for (int j0 = 0; j0 < scnt; j0 += 4) {
            int nb = (scnt - j0 < 4) ? (scnt - j0) : 4;
            int kk[4];
            for (int t = 0; t < nb; ++t) kk[t] = slist[j0 + t];
            eval4(kk, nb);
        }
    }

    const float4* wr = reinterpret_cast<const float4*>(w + (size_t)bi * CDIM);
    float4 qa = wr[lane * 2], qb = wr[lane * 2 + 1];
    float4 oa, ob;
    oa.x = xa.x + (qa.x - xa.x); oa.y = xa.y + (qa.y - xa.y);
    oa.z = xa.z + (qa.z - xa.z); oa.w = xa.w + (qa.w - xa.w);
    ob.x = xb.x + (qb.x - xb.x); ob.y = xb.y + (qb.y - xb.y);
    ob.z = xb.z + (qb.z - xb.z); ob.w = xb.w + (qb.w - xb.w);
    float4* og = reinterpret_cast<float4*>(out + (size_t)row * CDIM);
    og[lane * 2] = oa;
    og[lane * 2 + 1] = ob;
    if (lane == 0) out[(size_t)N_ROWS * CDIM + row] = (float)bi;
}

// ---------------------------------------------------------------------------
extern "C" void kernel_launch(void* const* d_in, const int* in_sizes, int n_in,
                              void* d_out, int out_size) {
    const float* x = reinterpret_cast<const float*>(d_in[0]);   // (8,4096,256)
    const float* w = reinterpret_cast<const float*>(d_in[1]);   // (8192,256)
    float* out = reinterpret_cast<float*>(d_out);

    static bool attr_set = false;
    if (!attr_set) {
        cudaFuncSetAttribute(vq_main_kernel,
                             cudaFuncAttributeMaxDynamicSharedMemorySize,
                             SMEM_BYTES);
        attr_set = true;
    }

    vq_conv_w<<<(KCODES * CDIM / 8) / 256, 256>>>(w);
    vq_prep_x<<<(N_ROWS * 32) / 256, 256>>>(x);
    vq_main_kernel<<<dim3(N_ROWS / MT, NSPLIT), THREADS, SMEM_BYTES>>>();
    vq_rescore_kernel<<<N_ROWS / 8, 256>>>(x, w, out);
}

// round 15
// speedup vs baseline: 1.0610x; 1.0610x over previous
#include <cuda_runtime.h>
#include <cuda_bf16.h>
#include <cstdint>

// ============================================================================
// VectorQuantizer via mma.sync (bf16 HMMA) screening GEMM + exact fp32 rescore.
// R15: main kernel = R13/R10 verbatim (at the measured ~512 MACs/cyc/SM
//      legacy-mma wall). Consolidation round:
//      - unified per-row candidate store (u64 score||idx, one count/row)
//      - single fused prep kernel (xnorm+conv_x+cnt-zero and conv_w)
//      - rescore phase-1 loads drop from 16 per-split stripes to 1-2 u64s/lane
// ============================================================================

#define N_ROWS   32768
#define CDIM     256
#define KCODES   8192
#define NSPLIT   8
#define KPER     (KCODES / NSPLIT)        // 1024
#define MT       256                      // rows per CTA
#define NT_TILE  128                      // codes per tile
#define NTILES   (KPER / NT_TILE)         // 8
#define NCHUNKS  (NTILES * 2)             // 16 (tile x k-half)
#define THREADS  512
#define LCAP     24                       // per-thread local buffer (main)
#define CAPR     48                       // per-row candidate capacity
#define SCAP     48                       // rescore survivor list capacity
#define MARGIN   1.4e-4f

#define ASTRIDE  528                      // A smem row stride (bytes)
#define ABYTES   (MT * ASTRIDE)           // 135168
#define BSTRIDE  272                      // B chunk row stride (128 k = 256B)
#define BCHUNK   (NT_TILE * BSTRIDE)      // 34816
#define SMEM_BYTES (ABYTES + 2 * BCHUNK)  // 204800

typedef unsigned long long u64;

__device__ __nv_bfloat16 g_xh[(size_t)N_ROWS * CDIM];   // 16 MB
__device__ __nv_bfloat16 g_wh[(size_t)KCODES * CDIM];   //  4 MB
__device__ float g_xnorm[N_ROWS];
__device__ int   g_rcnt[N_ROWS];
__device__ u64   g_cand[N_ROWS][CAPR];                  // 12.6 MB

__device__ __forceinline__ uint32_t smem_u32(const void* p) {
    uint32_t a;
    asm("{ .reg .u64 t; cvta.to.shared.u64 t, %1; cvt.u32.u64 %0, t; }"
        : "=r"(a) : "l"(p));
    return a;
}
__device__ __forceinline__ void ldsm4(uint32_t* r, uint32_t addr) {
    asm volatile("ldmatrix.sync.aligned.m8n8.x4.shared.b16 {%0,%1,%2,%3}, [%4];"
                 : "=r"(r[0]), "=r"(r[1]), "=r"(r[2]), "=r"(r[3]) : "r"(addr));
}
__device__ __forceinline__ void mma16816(float* c, const uint32_t* a,
                                         const uint32_t* b) {
    asm volatile(
        "mma.sync.aligned.m16n8k16.row.col.f32.bf16.bf16.f32 "
        "{%0,%1,%2,%3}, {%4,%5,%6,%7}, {%8,%9}, {%0,%1,%2,%3};"
        : "+f"(c[0]), "+f"(c[1]), "+f"(c[2]), "+f"(c[3])
        : "r"(a[0]), "r"(a[1]), "r"(a[2]), "r"(a[3]), "r"(b[0]), "r"(b[1]));
}
__device__ __forceinline__ void cp16(uint32_t saddr, const void* g) {
    asm volatile("cp.async.cg.shared.global [%0], [%1], 16;"
                 :: "r"(saddr), "l"(g) : "memory");
}
#define CP_COMMIT() asm volatile("cp.async.commit_group;" ::: "memory")
#define CP_WAIT0()  asm volatile("cp.async.wait_group 0;" ::: "memory")
#define CP_WAIT1()  asm volatile("cp.async.wait_group 1;" ::: "memory")

// ---------------------------------------------------------------------------
// Fused prep: warps [0, N_ROWS) handle x rows (xnorm byte-identical to all
// passing rounds + bf16 convert + per-row count zero); warps [N_ROWS,
// N_ROWS+KCODES) convert w codes.
// ---------------------------------------------------------------------------
__global__ void vq_prep(const float* __restrict__ x,
                        const float* __restrict__ w) {
    int gw   = (blockIdx.x * blockDim.x + threadIdx.x) >> 5;
    int lane = threadIdx.x & 31;
    if (gw < N_ROWS) {
        int row = gw;
        const float4* xr =
            reinterpret_cast<const float4*>(x + (size_t)row * CDIM);
        __nv_bfloat162* o =
            reinterpret_cast<__nv_bfloat162*>(g_xh + (size_t)row * CDIM);
        float s = 0.0f;
        #pragma unroll
        for (int i = 0; i < 2; ++i) {
            int j = lane + 32 * i;
            float4 v = xr[j];
            s = fmaf(v.x, v.x, s); s = fmaf(v.y, v.y, s);
            s = fmaf(v.z, v.z, s); s = fmaf(v.w, v.w, s);
            o[2 * j]     = __floats2bfloat162_rn(v.x, v.y);
            o[2 * j + 1] = __floats2bfloat162_rn(v.z, v.w);
        }
        #pragma unroll
        for (int of = 16; of > 0; of >>= 1)
            s += __shfl_xor_sync(0xffffffffu, s, of);
        if (lane == 0) {
            g_xnorm[row] = s;
            g_rcnt[row]  = 0;
        }
    } else {
        int code = gw - N_ROWS;
        const float4* wr =
            reinterpret_cast<const float4*>(w + (size_t)code * CDIM);
        float4 a = wr[lane * 2], b = wr[lane * 2 + 1];
        __nv_bfloat162 h[4];
        h[0] = __floats2bfloat162_rn(a.x, a.y);
        h[1] = __floats2bfloat162_rn(a.z, a.w);
        h[2] = __floats2bfloat162_rn(b.x, b.y);
        h[3] = __floats2bfloat162_rn(b.z, b.w);
        *reinterpret_cast<uint4*>(g_wh + (size_t)code * CDIM + lane * 8) =
            *reinterpret_cast<uint4*>(h);
    }
}

// ---------------------------------------------------------------------------
// Screening GEMM — loop VERBATIM from R10/R13 (the 516.2us PASS).
// Grid (128 row-tiles, 8 splits), 512 threads (16 warps); warp tile 32x64;
// A resident; B streamed as 16 chunks in a 2-deep cp.async ring.
// Flush writes to the unified per-row candidate store.
// ---------------------------------------------------------------------------
__global__ void __launch_bounds__(THREADS, 1)
vq_main_kernel() {
    extern __shared__ char smem[];
    const uint32_t sA = smem_u32(smem);
    const uint32_t sB = sA + ABYTES;

    const int tid  = threadIdx.x;
    const int wid  = tid >> 5;
    const int lane = tid & 31;
    const int wm   = wid >> 1;            // 0..7  (32-row slabs)
    const int wn   = wid & 1;             // 0..1  (64-col slabs)
    const int m0   = blockIdx.x * MT;
    const int split = blockIdx.y;
    const char* whb = reinterpret_cast<const char*>(g_wh);

    // ---- A: 256 rows x 256 bf16 into smem (stride 528B) ----
    const uint4* xh4 = reinterpret_cast<const uint4*>(g_xh);
    #pragma unroll
    for (int it = 0; it < 16; ++it) {
        int i = tid + it * THREADS;
        int r = i >> 5, c = i & 31;
        *reinterpret_cast<uint4*>(smem + r * ASTRIDE + c * 16) =
            xh4[(size_t)(m0 + r) * 32 + c];
    }

    auto issue_chunk = [&](int c) {
        int g0 = split * KPER + (c >> 1) * NT_TILE;
        int h  = c & 1;
        uint32_t bs = sB + (uint32_t)((c & 1) * BCHUNK);
        #pragma unroll
        for (int it = 0; it < 4; ++it) {
            int i = tid + it * THREADS;
            int r = i >> 4, q = i & 15;
            cp16(bs + (uint32_t)(r * BSTRIDE + q * 16),
                 whb + (size_t)(g0 + r) * 512 + h * 256 + q * 16);
        }
        CP_COMMIT();
    };

    issue_chunk(0);
    issue_chunk(1);

    const uint32_t aAddr = sA + (uint32_t)(wm * 32 + (lane & 15)) * ASTRIDE
                              + (uint32_t)((lane >> 4) << 4);
    const uint32_t bLane = (uint32_t)(wn * 64 + (lane & 7) + ((lane >> 4) << 3)) * BSTRIDE
                              + (uint32_t)(((lane >> 3) & 1) << 4);

    float xnr[4];
    #pragma unroll
    for (int mf = 0; mf < 2; ++mf)
        #pragma unroll
        for (int h = 0; h < 2; ++h)
            xnr[mf * 2 + h] = g_xnorm[m0 + wm * 32 + mf * 16 + (lane >> 2) + h * 8];

    float run[4];
    #pragma unroll
    for (int i = 0; i < 4; ++i) run[i] = 3.4e38f;

    float lsc[LCAP];
    int   lci[LCAP];
    int   ltot = 0;

    float acc[2][8][4];
    #pragma unroll
    for (int mf = 0; mf < 2; ++mf)
        #pragma unroll
        for (int nf = 0; nf < 8; ++nf)
            #pragma unroll
            for (int c = 0; c < 4; ++c) acc[mf][nf][c] = 0.0f;

    for (int c = 0; c < NCHUNKS; ++c) {
        if (c < NCHUNKS - 1) CP_WAIT1(); else CP_WAIT0();
        __syncthreads();

        const uint32_t bBuf = sB + (uint32_t)((c & 1) * BCHUNK) + bLane;
        const uint32_t hOff = (uint32_t)((c & 1) * 256);

        #pragma unroll
        for (int k = 0; k < 8; ++k) {
            const uint32_t ko = (uint32_t)(k * 32);
            uint32_t a[2][4], b[4][4];
            ldsm4(a[0], aAddr + hOff + ko);
            ldsm4(a[1], aAddr + (uint32_t)(16 * ASTRIDE) + hOff + ko);
            #pragma unroll
            for (int p = 0; p < 4; ++p)
                ldsm4(b[p], bBuf + (uint32_t)(p * 16 * BSTRIDE) + ko);
            #pragma unroll
            for (int mf = 0; mf < 2; ++mf) {
                #pragma unroll
                for (int p = 0; p < 4; ++p) {
                    mma16816(acc[mf][p * 2 + 0], a[mf], &b[p][0]);
                    mma16816(acc[mf][p * 2 + 1], a[mf], &b[p][2]);
                }
            }
        }

        if (c & 1) {
            const int nt = c >> 1;
            const int nTileBase = split * KPER + nt * NT_TILE + wn * 64 + 2 * (lane & 3);
            #pragma unroll
            for (int mf = 0; mf < 2; ++mf) {
                #pragma unroll
                for (int h = 0; h < 2; ++h) {
                    const int rsel = mf * 2 + h;
                    float xnv = xnr[rsel];
                    float s[16];
                    float tmin = 3.4e38f;
                    #pragma unroll
                    for (int nf = 0; nf < 8; ++nf) {
                        s[nf * 2]     = fmaf(-2.0f, acc[mf][nf][h * 2],     xnv);
                        s[nf * 2 + 1] = fmaf(-2.0f, acc[mf][nf][h * 2 + 1], xnv);
                        tmin = fminf(tmin, fminf(s[nf * 2], s[nf * 2 + 1]));
                    }
                    float q = fminf(tmin, __shfl_xor_sync(0xffffffffu, tmin, 1));
                    q = fminf(q, __shfl_xor_sync(0xffffffffu, q, 2));
                    float thr = fminf(run[rsel], q) + MARGIN;
                    run[rsel] = fminf(run[rsel], q);
                    #pragma unroll
                    for (int nf = 0; nf < 8; ++nf) {
                        #pragma unroll
                        for (int j = 0; j < 2; ++j) {
                            if (s[nf * 2 + j] <= thr) {
                                if (ltot < LCAP) {
                                    lsc[ltot] = s[nf * 2 + j];
                                    lci[ltot] = (nTileBase + nf * 8 + j) | (rsel << 13);
                                }
                                ltot++;
                            }
                        }
                    }
                }
            }
            #pragma unroll
            for (int mf = 0; mf < 2; ++mf)
                #pragma unroll
                for (int nf = 0; nf < 8; ++nf)
                    #pragma unroll
                    for (int cc = 0; cc < 4; ++cc) acc[mf][nf][cc] = 0.0f;
        }

        __syncthreads();
        if (c + 2 < NCHUNKS) issue_chunk(c + 2);
    }

    // ---- flush to unified per-row store ----
    {
        int rowbase[4];
        #pragma unroll
        for (int mf = 0; mf < 2; ++mf)
            #pragma unroll
            for (int h = 0; h < 2; ++h)
                rowbase[mf * 2 + h] = m0 + wm * 32 + mf * 16 + (lane >> 2) + h * 8;

        if (ltot > LCAP) {
            // overflow (tail-negligible): force full exact scan for these rows
            #pragma unroll
            for (int r = 0; r < 4; ++r)
                atomicAdd(&g_rcnt[rowbase[r]], CAPR + 1);
        } else {
            for (int j = 0; j < ltot; ++j) {
                float s  = lsc[j];
                int   e  = lci[j];
                int   rs = e >> 13;
                if (s <= run[rs] + MARGIN) {
                    int row = rowbase[rs];
                    int slot = atomicAdd(&g_rcnt[row], 1);
                    if (slot < CAPR)
                        g_cand[row][slot] =
                            ((u64)__float_as_uint(s) << 32) | (u64)(e & 8191);
                }
            }
        }
    }
}

// ---------------------------------------------------------------------------
// Rescore + finalize. One warp per row; unified candidate list; batched
// 4-wide exact evals (order-independent lowest-index argmin comparator).
// ---------------------------------------------------------------------------
__global__ void __launch_bounds__(256)
vq_rescore_kernel(const float* __restrict__ x, const float* __restrict__ w,
                  float* __restrict__ out) {
    __shared__ int slist_s[8][SCAP];
    int wid = threadIdx.x >> 5, lane = threadIdx.x & 31;
    int row = blockIdx.x * 8 + wid;
    int* slist = slist_s[wid];

    const float4* xr = reinterpret_cast<const float4*>(x + (size_t)row * CDIM);
    float4 xa = xr[lane * 2], xb = xr[lane * 2 + 1];
    float xn = g_xnorm[row];

    int cnt = g_rcnt[row];
    bool scan_all = (cnt > CAPR);

    float bv = 3.4e38f;
    int   bi = 0x7fffffff;

    auto eval4 = [&](const int* kk, int nb) {
        float4 wa[4], wb[4];
        for (int t = 0; t < nb; ++t) {
            const float4* wr =
                reinterpret_cast<const float4*>(w + (size_t)kk[t] * CDIM);
            wa[t] = wr[lane * 2];
            wb[t] = wr[lane * 2 + 1];
        }
        float d[4];
        for (int t = 0; t < nb; ++t) {
            float dd = 0.0f;
            dd = fmaf(xa.x, wa[t].x, dd); dd = fmaf(xa.y, wa[t].y, dd);
            dd = fmaf(xa.z, wa[t].z, dd); dd = fmaf(xa.w, wa[t].w, dd);
            dd = fmaf(xb.x, wb[t].x, dd); dd = fmaf(xb.y, wb[t].y, dd);
            dd = fmaf(xb.z, wb[t].z, dd); dd = fmaf(xb.w, wb[t].w, dd);
            d[t] = dd;
        }
        #pragma unroll
        for (int o = 16; o > 0; o >>= 1)
            for (int t = 0; t < nb; ++t)
                d[t] += __shfl_xor_sync(0xffffffffu, d[t], o);
        for (int t = 0; t < nb; ++t) {
            float s = fmaf(-2.0f, d[t], xn);
            if (s < bv || (s == bv && kk[t] < bi)) { bv = s; bi = kk[t]; }
        }
    };

    if (scan_all) {
        // correctness net: exact scan of all codes (never expected)
        int kk[4];
        for (int k = 0; k < KCODES; k += 4) {
            kk[0] = k; kk[1] = k + 1; kk[2] = k + 2; kk[3] = k + 3;
            eval4(kk, 4);
        }
    } else {
        // phase 1: load candidates (<= 2 u64 per lane), approx min
        float cs[2] = {3.4e38f, 3.4e38f};
        int   ci[2] = {0, 0};
        #pragma unroll
        for (int t = 0; t < 2; ++t) {
            int j = lane + t * 32;
            if (j < cnt && j < CAPR) {
                u64 v = g_cand[row][j];
                cs[t] = __uint_as_float((uint32_t)(v >> 32));
                ci[t] = (int)(v & 0xffffffffu);
            }
        }
        float m = fminf(cs[0], cs[1]);
        #pragma unroll
        for (int o = 16; o > 0; o >>= 1)
            m = fminf(m, __shfl_xor_sync(0xffffffffu, m, o));
        float thr = m + MARGIN;

        // phase 2: compact survivors + batched evals
        int scnt = 0;
        #pragma unroll
        for (int t = 0; t < 2; ++t) {
            unsigned msk = __ballot_sync(0xffffffffu, cs[t] <= thr);
            while (msk) {
                int b = __ffs(msk) - 1;
                msk &= msk - 1;
                int k = __shfl_sync(0xffffffffu, ci[t], b);
                if (scnt < SCAP) slist[scnt] = k;
                scnt++;
            }
        }
        for (int j0 = 0; j0 < scnt; j0 += 4) {
            int nb = (scnt - j0 < 4) ? (scnt - j0) : 4;
            int kk[4];
            for (int t = 0; t < nb; ++t) kk[t] = slist[j0 + t];
            eval4(kk, nb);
        }
    }

    const float4* wr = reinterpret_cast<const float4*>(w + (size_t)bi * CDIM);
    float4 qa = wr[lane * 2], qb = wr[lane * 2 + 1];
    float4 oa, ob;
    oa.x = xa.x + (qa.x - xa.x); oa.y = xa.y + (qa.y - xa.y);
    oa.z = xa.z + (qa.z - xa.z); oa.w = xa.w + (qa.w - xa.w);
    ob.x = xb.x + (qb.x - xb.x); ob.y = xb.y + (qb.y - xb.y);
    ob.z = xb.z + (qb.z - xb.z); ob.w = xb.w + (qb.w - xb.w);
    float4* og = reinterpret_cast<float4*>(out + (size_t)row * CDIM);
    og[lane * 2] = oa;
    og[lane * 2 + 1] = ob;
    if (lane == 0) out[(size_t)N_ROWS * CDIM + row] = (float)bi;
}

// ---------------------------------------------------------------------------
extern "C" void kernel_launch(void* const* d_in, const int* in_sizes, int n_in,
                              void* d_out, int out_size) {
    const float* x = reinterpret_cast<const float*>(d_in[0]);   // (8,4096,256)
    const float* w = reinterpret_cast<const float*>(d_in[1]);   // (8192,256)
    float* out = reinterpret_cast<float*>(d_out);

    static bool attr_set = false;
    if (!attr_set) {
        cudaFuncSetAttribute(vq_main_kernel,
                             cudaFuncAttributeMaxDynamicSharedMemorySize,
                             SMEM_BYTES);
        attr_set = true;
    }

    vq_prep<<<((N_ROWS + KCODES) * 32) / 256, 256>>>(x, w);
    vq_main_kernel<<<dim3(N_ROWS / MT, NSPLIT), THREADS, SMEM_BYTES>>>();
    vq_rescore_kernel<<<N_ROWS / 8, 256>>>(x, w, out);
}